// round 11
// baseline (speedup 1.0000x reference)
#include <cuda_runtime.h>

// Problem constants (fixed for this instance)
#define HW_   262144          // H*W = 512*512
#define D_    32
#define C_    19
#define N_    2097152         // B*H*W
#define TILE_ 256
#define NT_   8192            // N / TILE_
#define GRID_ 444             // 3 blocks/SM * 148 (smem-limited occupancy)
#define PITCH 34              // bucket row pitch (floats)
#define SMEMB (2 * TILE_ * PITCH * 4)   // 69632 bytes dynamic smem
#define EPS_  1e-8f

// ---------------- scratch (zero-initialized device globals) -----------------
// The in-kernel epilogue resets all of these, so every graph replay is clean.
__device__ float    g_sumv[C_ * D_];   // per-class sums of x
__device__ float    g_sumn[C_ * D_];   // per-class sums of x/||x||
__device__ float    g_cnt[C_];         // per-class counts
__device__ unsigned g_tile;            // dynamic work counter
__device__ unsigned g_done;            // finished-block counter

extern __shared__ float dynsmem[];     // bucket[2][TILE_ * PITCH]

__global__ void __launch_bounds__(256)
k_all(const float* __restrict__ in, const void* __restrict__ tgt,
      float* __restrict__ out) {
    float* const bkt[2] = { dynsmem, dynsmem + TILE_ * PITCH };
    __shared__ int scount[2][C_];
    __shared__ int s_nxt[2];
    __shared__ int s_first, s_is64, s_last;

    const int t    = threadIdx.x;
    const int w    = t >> 5;
    const int lane = t & 31;
    const unsigned FULL = 0xffffffffu;

    if (t < C_) { scount[0][t] = 0; scount[1][t] = 0; }
    if (t == 0) {
        // int64 labels in [0,19): every odd 32-bit word is 0.
        const unsigned* wd = (const unsigned*)tgt;
        int is64 = 1;
        #pragma unroll
        for (int k = 0; k < 16; k++)
            if (wd[2 * k + 1] != 0u) is64 = 0;
        s_is64 = is64;
        s_first = (int)atomicAdd(&g_tile, 1u);
    }
    __syncthreads();
    const int is64 = s_is64;
    const long long* t64 = (const long long*)tgt;
    const int*       t32 = (const int*)tgt;

    int tile = s_first;

    // register accumulators: warp w owns classes w, w+8, w+16
    float sv[3] = {0.f, 0.f, 0.f};
    float sn[3] = {0.f, 0.f, 0.f};
    float cr[3] = {0.f, 0.f, 0.f};

    // prologue: load tile's vectors + label
    float v[D_];
    int lab = 0;
    if (tile < NT_) {
        const int p  = tile * TILE_ + t;
        const int b  = p >> 18;
        const int hw = p & (HW_ - 1);
        const float* bp = in + (size_t)b * ((size_t)D_ * HW_) + hw;
        #pragma unroll
        for (int d = 0; d < D_; ++d) v[d] = bp[(size_t)d * HW_];
        lab = is64 ? (int)t64[p] : t32[p];
    }

    int parity = 0;
    while (tile < NT_) {
        // fetch tile id one step ahead (slot `parity`; read after sync2)
        if (t == 0) s_nxt[parity] = (int)atomicAdd(&g_tile, 1u);

        // r = 1/||x||
        float ss = 0.f;
        #pragma unroll
        for (int d = 0; d < D_; ++d) ss = fmaf(v[d], v[d], ss);
        float r = rsqrtf(fmaxf(ss, 1e-24f));

        // histogram + within-class rank
        unsigned m = __match_any_sync(FULL, lab);
        int lead   = __ffs(m) - 1;
        int rank   = __popc(m & ((1u << lane) - 1u));
        int wofs   = 0;
        if (lane == lead) wofs = atomicAdd(&scount[parity][lab], __popc(m));
        wofs = __shfl_sync(FULL, wofs, lead);
        __syncthreads();                       // sync1: histogram visible

        // redundant per-warp exclusive scan of the 19 counts
        int cv = (lane < C_) ? scount[parity][lane] : 0;
        int sc = cv;
        #pragma unroll
        for (int o = 1; o < 32; o <<= 1) {
            int nn = __shfl_up_sync(FULL, sc, o);
            if (lane >= o) sc += nn;
        }
        int mybase = __shfl_sync(FULL, sc - cv, lab);

        // scatter vector + r into class-sorted bucket (float2 STS)
        float* buf = bkt[parity];
        const int slot = mybase + wofs + rank;
        float2* bs2 = (float2*)&buf[slot * PITCH];
        #pragma unroll
        for (int k = 0; k < 16; ++k)
            bs2[k] = make_float2(v[2 * k], v[2 * k + 1]);
        buf[slot * PITCH + 32] = r;

        // zero the other histogram for the next iteration
        if (t < C_) scount[1 - parity][t] = 0;
        __syncthreads();                       // sync2: scatter + s_nxt visible

        // prefetch next tile's loads NOW; they fly during the gather
        const int nxt = s_nxt[parity];
        if (nxt < NT_) {
            const int p  = nxt * TILE_ + t;
            const int b  = p >> 18;
            const int hw = p & (HW_ - 1);
            const float* bp = in + (size_t)b * ((size_t)D_ * HW_) + hw;
            #pragma unroll
            for (int d = 0; d < D_; ++d) v[d] = bp[(size_t)d * HW_];
            lab = is64 ? (int)t64[p] : t32[p];
        }

        // gather: register accumulation per owned class (lane = dim)
        #pragma unroll
        for (int i = 0; i < 3; ++i) {
            const int c = w + 8 * i;
            if (c < C_) {
                const int bse = __shfl_sync(FULL, sc - cv, c);
                const int cc  = __shfl_sync(FULL, cv, c);
                cr[i] += (float)cc;
                float s0 = 0.f, n0 = 0.f, s1 = 0.f, n1 = 0.f;
                int k = 0;
                for (; k + 1 < cc; k += 2) {
                    const float* m0 = &buf[(bse + k) * PITCH];
                    const float* m1 = &buf[(bse + k + 1) * PITCH];
                    float a0 = m0[lane], r0 = m0[32];
                    float a1 = m1[lane], r1 = m1[32];
                    s0 += a0; n0 = fmaf(a0, r0, n0);
                    s1 += a1; n1 = fmaf(a1, r1, n1);
                }
                if (k < cc) {
                    const float* m0 = &buf[(bse + k) * PITCH];
                    float a0 = m0[lane], r0 = m0[32];
                    s0 += a0; n0 = fmaf(a0, r0, n0);
                }
                sv[i] += s0 + s1;
                sn[i] += n0 + n1;
            }
        }
        // no barrier: scatter(t+2) into this buffer is fenced by sync1(t+2)

        tile = nxt;
        parity ^= 1;
    }

    // flush per-block class totals
    #pragma unroll
    for (int i = 0; i < 3; ++i) {
        const int c = w + 8 * i;
        if (c < C_) {
            atomicAdd(&g_sumv[c * 32 + lane], sv[i]);
            atomicAdd(&g_sumn[c * 32 + lane], sn[i]);
            if (lane == 0) atomicAdd(&g_cnt[c], cr[i]);
        }
    }

    // ---- last-block epilogue (replaces k_final) ----
    __threadfence();
    if (t == 0) s_last = (atomicAdd(&g_done, 1u) == GRID_ - 1u) ? 1 : 0;
    __syncthreads();
    if (!s_last) return;

    float* cs    = bkt[0];           // 19*33 floats (bucket is free now)
    float* cn    = cs + C_ * 33;
    float* simA  = cn + C_;
    float* spres = simA + C_;
    float* srow  = spres + C_;

    if (t < C_) srow[t] = 0.f;
    #pragma unroll
    for (int i = 0; i < 3; ++i) {
        const int c = w + 8 * i;
        if (c < C_) {
            float count = g_cnt[c];
            float denom = fmaxf(count, 1.f);
            float ctr   = g_sumv[c * 32 + lane] / denom;
            float nsum  = g_sumn[c * 32 + lane];
            cs[c * 33 + lane] = ctr;
            g_sumv[c * 32 + lane] = 0.f;      // reset for next replay
            g_sumn[c * 32 + lane] = 0.f;

            float s = ctr * ctr;
            #pragma unroll
            for (int o = 16; o; o >>= 1) s += __shfl_xor_sync(FULL, s, o);
            float cnorm = sqrtf(s);

            float scd = nsum * ctr;           // seg_cos numerator
            #pragma unroll
            for (int o = 16; o; o >>= 1) scd += __shfl_xor_sync(FULL, scd, o);

            if (lane == 0) {
                bool pres = count > 0.f;
                float segcos = scd / fmaxf(cnorm, 1e-30f);
                cn[c]    = cnorm;
                simA[c]  = pres ? (1.f - segcos / denom) : 0.f;
                spres[c] = pres ? 1.f : 0.f;
                g_cnt[c] = 0.f;
            }
        }
    }
    if (t == 0) { g_tile = 0u; g_done = 0u; }
    __syncthreads();

    // pairwise diff terms of the 19x19 center-cosine matrix
    for (int idx = t; idx < C_ * C_; idx += 256) {
        const int ii = idx / C_;
        const int jj = idx - ii * C_;
        float dot = 0.f;
        #pragma unroll
        for (int dd = 0; dd < D_; ++dd)
            dot = fmaf(cs[ii * 33 + dd], cs[jj * 33 + dd], dot);
        float cosv = dot / fmaxf(cn[ii] * cn[jj], EPS_);
        float term = (ii == jj) ? (1.f - cosv) : fmaxf(cosv, 0.f);
        atomicAdd(&srow[ii], term);
    }
    __syncthreads();

    if (t < 32) {
        float tot = (t < C_) ? simA[t] + spres[t] * (srow[t] / (float)C_) : 0.f;
        #pragma unroll
        for (int o = 16; o; o >>= 1) tot += __shfl_xor_sync(FULL, tot, o);
        if (t == 0) out[0] = tot;
    }
}

// ---------------- launcher --------------------------------------------------
extern "C" void kernel_launch(void* const* d_in, const int* in_sizes, int n_in,
                              void* d_out, int out_size) {
    (void)in_sizes; (void)n_in; (void)out_size;
    const float* in  = (const float*)d_in[0];
    const void*  tgt = d_in[1];
    float*       out = (float*)d_out;

    cudaFuncSetAttribute(k_all, cudaFuncAttributeMaxDynamicSharedMemorySize,
                         SMEMB);
    k_all<<<GRID_, 256, SMEMB>>>(in, tgt, out);
}

// round 13
// speedup vs baseline: 1.1618x; 1.1618x over previous
#include <cuda_runtime.h>

// Problem constants (fixed for this instance)
#define HW_   262144          // H*W = 512*512
#define D_    32
#define C_    19
#define N_    2097152         // B*H*W
#define TILE_ 256
#define NT_   8192            // N / TILE_
#define GRID_ 740             // 5 blocks/SM * 148
#define PITCH 34              // bucket row pitch (floats)
#define EPS_  1e-8f

// ---------------- scratch (zero-initialized device globals) -----------------
// The in-kernel epilogue resets all of these, so every graph replay is clean.
__device__ float    g_sumv[C_ * D_];   // per-class sums of x
__device__ float    g_sumn[C_ * D_];   // per-class sums of x/||x||
__device__ float    g_cnt[C_];         // per-class counts
__device__ unsigned g_tile;            // dynamic work counter
__device__ unsigned g_done;            // finished-block counter

__global__ void __launch_bounds__(256, 5)
k_all(const float* __restrict__ in, const void* __restrict__ tgt,
      float* __restrict__ out) {
    __shared__ float bucket[TILE_ * PITCH];   // single buffer, slot-major
    __shared__ int   scount[2][C_];           // parity histograms
    __shared__ int   s_nxt[2];
    __shared__ int   s_first, s_is64, s_last;

    const int t    = threadIdx.x;
    const int w    = t >> 5;
    const int lane = t & 31;
    const unsigned FULL = 0xffffffffu;

    if (t < C_) { scount[0][t] = 0; scount[1][t] = 0; }
    if (t == 0) {
        // int64 labels in [0,19): every odd 32-bit word is 0.
        const unsigned* wd = (const unsigned*)tgt;
        int is64 = 1;
        #pragma unroll
        for (int k = 0; k < 16; k++)
            if (wd[2 * k + 1] != 0u) is64 = 0;
        s_is64 = is64;
        s_first = (int)atomicAdd(&g_tile, 1u);
    }
    __syncthreads();
    const int is64 = s_is64;
    const long long* t64 = (const long long*)tgt;
    const int*       t32 = (const int*)tgt;

    int tile = s_first;

    // register accumulators: warp w owns classes w, w+8, w+16
    float sv[3] = {0.f, 0.f, 0.f};
    float sn[3] = {0.f, 0.f, 0.f};
    float cr[3] = {0.f, 0.f, 0.f};

    int parity = 0;
    while (tile < NT_) {
        // fetch next tile id early (visible after syncA)
        if (t == 0) s_nxt[parity] = (int)atomicAdd(&g_tile, 1u);

        // load this tile's vectors + label (coalesced; LDGs overlap hist work)
        const int p  = tile * TILE_ + t;
        const int b  = p >> 18;
        const int hw = p & (HW_ - 1);
        const float* bp = in + (size_t)b * ((size_t)D_ * HW_) + hw;
        float v[D_];
        float ss = 0.f;
        #pragma unroll
        for (int d = 0; d < D_; ++d) {
            v[d] = bp[(size_t)d * HW_];
            ss = fmaf(v[d], v[d], ss);
        }
        float r = rsqrtf(fmaxf(ss, 1e-24f));      // 1/||x||
        int lab = is64 ? (int)t64[p] : t32[p];

        // histogram + within-class rank
        unsigned m = __match_any_sync(FULL, lab);
        int lead   = __ffs(m) - 1;
        int rank   = __popc(m & ((1u << lane) - 1u));
        int wofs   = 0;
        if (lane == lead) wofs = atomicAdd(&scount[parity][lab], __popc(m));
        wofs = __shfl_sync(FULL, wofs, lead);
        __syncthreads();   // syncA: hist + s_nxt visible; prev gather done

        // redundant per-warp exclusive scan of the 19 counts
        int cv = (lane < C_) ? scount[parity][lane] : 0;
        int sc = cv;
        #pragma unroll
        for (int o = 1; o < 32; o <<= 1) {
            int nn = __shfl_up_sync(FULL, sc, o);
            if (lane >= o) sc += nn;
        }
        int mybase = __shfl_sync(FULL, sc - cv, lab);

        // scatter vector + r into class-sorted bucket (float2 STS)
        const int slot = mybase + wofs + rank;
        float2* bs2 = (float2*)&bucket[slot * PITCH];
        #pragma unroll
        for (int k = 0; k < 16; ++k)
            bs2[k] = make_float2(v[2 * k], v[2 * k + 1]);
        bucket[slot * PITCH + 32] = r;

        // zero the other-parity histogram for the next iteration
        if (t < C_) scount[1 - parity][t] = 0;
        const int nxt = s_nxt[parity];
        __syncthreads();   // syncB: scatter visible

        // gather: register accumulation per owned class (lane = dim)
        #pragma unroll
        for (int i = 0; i < 3; ++i) {
            const int c = w + 8 * i;
            if (c < C_) {
                const int bse = __shfl_sync(FULL, sc - cv, c);
                const int cc  = __shfl_sync(FULL, cv, c);
                cr[i] += (float)cc;
                float s0 = 0.f, n0 = 0.f, s1 = 0.f, n1 = 0.f;
                int k = 0;
                for (; k + 1 < cc; k += 2) {
                    const float* m0 = &bucket[(bse + k) * PITCH];
                    const float* m1 = &bucket[(bse + k + 1) * PITCH];
                    float a0 = m0[lane], r0 = m0[32];
                    float a1 = m1[lane], r1 = m1[32];
                    s0 += a0; n0 = fmaf(a0, r0, n0);
                    s1 += a1; n1 = fmaf(a1, r1, n1);
                }
                if (k < cc) {
                    const float* m0 = &bucket[(bse + k) * PITCH];
                    float a0 = m0[lane], r0 = m0[32];
                    s0 += a0; n0 = fmaf(a0, r0, n0);
                }
                sv[i] += s0 + s1;
                sn[i] += n0 + n1;
            }
        }
        // no trailing barrier: next iteration's syncA orders bucket reuse

        tile = nxt;
        parity ^= 1;
    }

    // flush per-block class totals
    #pragma unroll
    for (int i = 0; i < 3; ++i) {
        const int c = w + 8 * i;
        if (c < C_) {
            atomicAdd(&g_sumv[c * 32 + lane], sv[i]);
            atomicAdd(&g_sumn[c * 32 + lane], sn[i]);
            if (lane == 0) atomicAdd(&g_cnt[c], cr[i]);
        }
    }

    // ---- last-block epilogue (replaces a separate k_final launch) ----
    __threadfence();
    if (t == 0) s_last = (atomicAdd(&g_done, 1u) == GRID_ - 1u) ? 1 : 0;
    __syncthreads();
    if (!s_last) return;

    float* cs    = bucket;           // 19*33 floats (bucket is free now)
    float* cn    = cs + C_ * 33;
    float* simA  = cn + C_;
    float* spres = simA + C_;
    float* srow  = spres + C_;

    if (t < C_) srow[t] = 0.f;
    #pragma unroll
    for (int i = 0; i < 3; ++i) {
        const int c = w + 8 * i;
        if (c < C_) {
            float count = g_cnt[c];
            float denom = fmaxf(count, 1.f);
            float ctr   = g_sumv[c * 32 + lane] / denom;
            float nsum  = g_sumn[c * 32 + lane];
            cs[c * 33 + lane] = ctr;
            g_sumv[c * 32 + lane] = 0.f;      // reset for next replay
            g_sumn[c * 32 + lane] = 0.f;

            float s = ctr * ctr;
            #pragma unroll
            for (int o = 16; o; o >>= 1) s += __shfl_xor_sync(FULL, s, o);
            float cnorm = sqrtf(s);

            float scd = nsum * ctr;           // seg_cos numerator
            #pragma unroll
            for (int o = 16; o; o >>= 1) scd += __shfl_xor_sync(FULL, scd, o);

            if (lane == 0) {
                bool pres = count > 0.f;
                float segcos = scd / fmaxf(cnorm, 1e-30f);
                cn[c]    = cnorm;
                simA[c]  = pres ? (1.f - segcos / denom) : 0.f;
                spres[c] = pres ? 1.f : 0.f;
                g_cnt[c] = 0.f;
            }
        }
    }
    if (t == 0) { g_tile = 0u; g_done = 0u; }
    __syncthreads();

    // pairwise diff terms of the 19x19 center-cosine matrix
    for (int idx = t; idx < C_ * C_; idx += 256) {
        const int ii = idx / C_;
        const int jj = idx - ii * C_;
        float dot = 0.f;
        #pragma unroll
        for (int dd = 0; dd < D_; ++dd)
            dot = fmaf(cs[ii * 33 + dd], cs[jj * 33 + dd], dot);
        float cosv = dot / fmaxf(cn[ii] * cn[jj], EPS_);
        float term = (ii == jj) ? (1.f - cosv) : fmaxf(cosv, 0.f);
        atomicAdd(&srow[ii], term);
    }
    __syncthreads();

    if (t < 32) {
        float tot = (t < C_) ? simA[t] + spres[t] * (srow[t] / (float)C_) : 0.f;
        #pragma unroll
        for (int o = 16; o; o >>= 1) tot += __shfl_xor_sync(FULL, tot, o);
        if (t == 0) out[0] = tot;
    }
}

// ---------------- launcher --------------------------------------------------
extern "C" void kernel_launch(void* const* d_in, const int* in_sizes, int n_in,
                              void* d_out, int out_size) {
    (void)in_sizes; (void)n_in; (void)out_size;
    const float* in  = (const float*)d_in[0];
    const void*  tgt = d_in[1];
    float*       out = (float*)d_out;

    k_all<<<GRID_, 256>>>(in, tgt, out);
}

// round 14
// speedup vs baseline: 1.2710x; 1.0939x over previous
#include <cuda_runtime.h>

// Problem constants (fixed for this instance)
#define HW_   262144          // H*W = 512*512
#define D_    32
#define C_    19
#define N_    2097152         // B*H*W
#define TILE_ 256
#define NT_   8192            // N / TILE_
#define GRID_ 592             // 4 blocks/SM * 148
#define PITCH 34              // bucket row pitch (floats)
#define EPS_  1e-8f

// ---------------- scratch (zero-initialized device globals) -----------------
// The in-kernel epilogue resets all of these, so every graph replay is clean.
__device__ float    g_sumv[C_ * D_];   // per-class sums of x
__device__ float    g_sumn[C_ * D_];   // per-class sums of x/||x||
__device__ float    g_cnt[C_];         // per-class counts
__device__ unsigned g_tile;            // dynamic work counter
__device__ unsigned g_done;            // finished-block counter

__global__ void __launch_bounds__(256, 4)
k_all(const float* __restrict__ in, const void* __restrict__ tgt,
      float* __restrict__ out) {
    __shared__ float bucket[TILE_ * PITCH];  // slot-major
    __shared__ int   scount[C_];
    __shared__ int   s_next;
    __shared__ int   s_is64, s_last;

    const int t    = threadIdx.x;
    const int w    = t >> 5;
    const int lane = t & 31;
    const unsigned FULL = 0xffffffffu;

    if (t == 0) {
        // int64 labels in [0,19): every odd 32-bit word is 0.
        const unsigned* wd = (const unsigned*)tgt;
        int is64 = 1;
        #pragma unroll
        for (int k = 0; k < 16; k++)
            if (wd[2 * k + 1] != 0u) is64 = 0;
        s_is64 = is64;
    }
    __syncthreads();
    const int is64 = s_is64;
    const long long* t64 = (const long long*)tgt;
    const int*       t32 = (const int*)tgt;

    // register accumulators: warp w owns classes w, w+8, w+16
    float sv[3] = {0.f, 0.f, 0.f};
    float sn[3] = {0.f, 0.f, 0.f};
    float cr[3] = {0.f, 0.f, 0.f};

    for (;;) {
        // fetch next tile + zero histogram (prev gather finished: loop-end sync)
        if (t == 0) s_next = (int)atomicAdd(&g_tile, 1u);
        if (t < C_) scount[t] = 0;
        __syncthreads();
        const int tile = s_next;
        if (tile >= NT_) break;

        const int p  = tile * TILE_ + t;          // this thread's pixel
        const int b  = p >> 18;
        const int hw = p & (HW_ - 1);
        const float* bp = in + (size_t)b * ((size_t)D_ * HW_) + hw;

        // coalesced: per d, 32 lanes cover one 128B line
        float v[D_];
        float ss = 0.f;
        #pragma unroll
        for (int d = 0; d < D_; ++d) {
            v[d] = bp[(size_t)d * HW_];
            ss = fmaf(v[d], v[d], ss);
        }
        float r = rsqrtf(fmaxf(ss, 1e-24f));      // 1/||x||
        int lab = is64 ? (int)t64[p] : t32[p];

        // histogram + within-class rank
        unsigned m  = __match_any_sync(FULL, lab);
        int lead    = __ffs(m) - 1;
        int rank    = __popc(m & ((1u << lane) - 1u));
        int wofs    = 0;
        if (lane == lead) wofs = atomicAdd(&scount[lab], __popc(m));
        wofs = __shfl_sync(FULL, wofs, lead);
        __syncthreads();

        // redundant per-warp exclusive scan of the 19 counts (no extra sync)
        int cv = (lane < C_) ? scount[lane] : 0;
        int sc = cv;
        #pragma unroll
        for (int o = 1; o < 32; o <<= 1) {
            int nn = __shfl_up_sync(FULL, sc, o);
            if (lane >= o) sc += nn;
        }
        int mybase = __shfl_sync(FULL, sc - cv, lab);   // sbase[lab]

        // scatter pixel vector + r into class-sorted bucket (float2 STS)
        const int slot = mybase + wofs + rank;
        float2* bs2 = (float2*)&bucket[slot * PITCH];
        #pragma unroll
        for (int k = 0; k < 16; ++k)
            bs2[k] = make_float2(v[2 * k], v[2 * k + 1]);
        bucket[slot * PITCH + 32] = r;
        __syncthreads();

        // gather: register accumulation per owned class (lane = dim)
        #pragma unroll
        for (int i = 0; i < 3; ++i) {
            const int c = w + 8 * i;
            if (c < C_) {
                const int bse = __shfl_sync(FULL, sc - cv, c); // sbase[c]
                const int cc  = __shfl_sync(FULL, cv, c);      // scount[c]
                cr[i] += (float)cc;
                float s0 = 0.f, n0 = 0.f, s1 = 0.f, n1 = 0.f;
                int k = 0;
                for (; k + 1 < cc; k += 2) {
                    const float* m0 = &bucket[(bse + k) * PITCH];
                    const float* m1 = &bucket[(bse + k + 1) * PITCH];
                    float a0 = m0[lane], r0 = m0[32];
                    float a1 = m1[lane], r1 = m1[32];
                    s0 += a0; n0 = fmaf(a0, r0, n0);
                    s1 += a1; n1 = fmaf(a1, r1, n1);
                }
                if (k < cc) {
                    const float* m0 = &bucket[(bse + k) * PITCH];
                    float a0 = m0[lane], r0 = m0[32];
                    s0 += a0; n0 = fmaf(a0, r0, n0);
                }
                sv[i] += s0 + s1;
                sn[i] += n0 + n1;
            }
        }
        __syncthreads();                           // bucket reuse barrier
    }

    // flush per-block class totals
    #pragma unroll
    for (int i = 0; i < 3; ++i) {
        const int c = w + 8 * i;
        if (c < C_) {
            atomicAdd(&g_sumv[c * 32 + lane], sv[i]);
            atomicAdd(&g_sumn[c * 32 + lane], sn[i]);
            if (lane == 0) atomicAdd(&g_cnt[c], cr[i]);
        }
    }

    // ---- last-block epilogue (replaces a separate k_final launch) ----
    __threadfence();
    if (t == 0) s_last = (atomicAdd(&g_done, 1u) == GRID_ - 1u) ? 1 : 0;
    __syncthreads();
    if (!s_last) return;

    float* cs    = bucket;           // 19*33 floats (bucket is free now)
    float* cn    = cs + C_ * 33;
    float* simA  = cn + C_;
    float* spres = simA + C_;
    float* srow  = spres + C_;

    if (t < C_) srow[t] = 0.f;
    #pragma unroll
    for (int i = 0; i < 3; ++i) {
        const int c = w + 8 * i;
        if (c < C_) {
            float count = g_cnt[c];
            float denom = fmaxf(count, 1.f);
            float ctr   = g_sumv[c * 32 + lane] / denom;
            float nsum  = g_sumn[c * 32 + lane];
            cs[c * 33 + lane] = ctr;
            g_sumv[c * 32 + lane] = 0.f;      // reset for next replay
            g_sumn[c * 32 + lane] = 0.f;

            float s = ctr * ctr;
            #pragma unroll
            for (int o = 16; o; o >>= 1) s += __shfl_xor_sync(FULL, s, o);
            float cnorm = sqrtf(s);

            float scd = nsum * ctr;           // seg_cos numerator
            #pragma unroll
            for (int o = 16; o; o >>= 1) scd += __shfl_xor_sync(FULL, scd, o);

            if (lane == 0) {
                bool pres = count > 0.f;
                float segcos = scd / fmaxf(cnorm, 1e-30f);
                cn[c]    = cnorm;
                simA[c]  = pres ? (1.f - segcos / denom) : 0.f;
                spres[c] = pres ? 1.f : 0.f;
                g_cnt[c] = 0.f;
            }
        }
    }
    if (t == 0) { g_tile = 0u; g_done = 0u; }
    __syncthreads();

    // pairwise diff terms of the 19x19 center-cosine matrix
    for (int idx = t; idx < C_ * C_; idx += 256) {
        const int ii = idx / C_;
        const int jj = idx - ii * C_;
        float dot = 0.f;
        #pragma unroll
        for (int dd = 0; dd < D_; ++dd)
            dot = fmaf(cs[ii * 33 + dd], cs[jj * 33 + dd], dot);
        float cosv = dot / fmaxf(cn[ii] * cn[jj], EPS_);
        float term = (ii == jj) ? (1.f - cosv) : fmaxf(cosv, 0.f);
        atomicAdd(&srow[ii], term);
    }
    __syncthreads();

    if (t < 32) {
        float tot = (t < C_) ? simA[t] + spres[t] * (srow[t] / (float)C_) : 0.f;
        #pragma unroll
        for (int o = 16; o; o >>= 1) tot += __shfl_xor_sync(FULL, tot, o);
        if (t == 0) out[0] = tot;
    }
}

// ---------------- launcher --------------------------------------------------
extern "C" void kernel_launch(void* const* d_in, const int* in_sizes, int n_in,
                              void* d_out, int out_size) {
    (void)in_sizes; (void)n_in; (void)out_size;
    const float* in  = (const float*)d_in[0];
    const void*  tgt = d_in[1];
    float*       out = (float*)d_out;

    k_all<<<GRID_, 256>>>(in, tgt, out);
}